// round 17
// baseline (speedup 1.0000x reference)
#include <cuda_runtime.h>
#include <cuda_fp16.h>

// CostVolumeManager: plane-sweep cost volume. B=1, S=8, C=16, H=64, W=96, D=64.
//
// v10: reduce gather WORK via cross-depth tap sharing.
//   Each thread owns depths (d, d+1). When both depths' bilinear indices
//   coincide (common: epipolar step < 1px for most bins), the second set of
//   8 tap loads is skipped -- bitwise-identical results, strictly fewer
//   L1 accesses. Also: Wp=104 (128B-aligned rows), vectorized pack pass.
//   Numeric core unchanged from v9 (fp16 tree-dot, magic floor, padded
//   zero-apron planes, fp32 accumulation).

namespace cvk {

constexpr int S = 8, C = 16, H = 64, W = 96, D = 64, N = H * W;
constexpr int Wp = 104, Hp = H + 4;        // rows 104*16B = 1664B = 13*128B
constexpr int NP = Hp * Wp;                // left apron 2, right apron 6
constexpr int SRC_PACK_BLOCKS = (S * 4 * (N / 4)) / 256;   // 192
constexpr int CUR_PACK_BLOCKS = (4 * (N / 4)) / 256;       // 24

// Static device scratch (zero-initialized at module load; pads never written).
__device__ uint4    g_srcA[S * NP];   // fp16 ch0..7  per padded pixel
__device__ uint4    g_srcB[S * NP];   // fp16 ch8..15 per padded pixel
__device__ unsigned g_curh[N * 8];    // fp16 cur feats: [n][8 x half2]

// ---------------------------------------------------------------- pack pass
// src part: thread = (s, 4-channel group h, 4 consecutive pixels).
// All loads are float4 over contiguous n (W % 4 == 0 -> no row crossing).
__global__ __launch_bounds__(256)
void pack_all(const float* __restrict__ src, const float* __restrict__ cur) {
    int bid = blockIdx.x;
    if (bid < SRC_PACK_BLOCKS) {
        int idx = bid * 256 + threadIdx.x;        // (s*4 + h)*(N/4) + n4
        int n4 = idx % (N / 4);
        int sh = idx / (N / 4);
        int h = sh & 3, s = sh >> 2;
        int n = n4 * 4;
        int y = n / W, x = n - y * W;
        const float* p = src + ((size_t)(s * C + 4 * h)) * N + n;
        float4 c0 = *reinterpret_cast<const float4*>(p);
        float4 c1 = *reinterpret_cast<const float4*>(p + N);
        float4 c2 = *reinterpret_cast<const float4*>(p + 2 * N);
        float4 c3 = *reinterpret_cast<const float4*>(p + 3 * N);
        const float* e0 = &c0.x; const float* e1 = &c1.x;
        const float* e2 = &c2.x; const float* e3 = &c3.x;
        uint2* plane = (h < 2) ? reinterpret_cast<uint2*>(g_srcA)
                               : reinterpret_cast<uint2*>(g_srcB);
        int ppb = (s * Hp + y + 2) * Wp + (x + 2);
#pragma unroll
        for (int i = 0; i < 4; i++) {
            __half2 a = __floats2half2_rn(e0[i], e1[i]);
            __half2 b = __floats2half2_rn(e2[i], e3[i]);
            uint2 v;
            v.x = *reinterpret_cast<unsigned*>(&a);
            v.y = *reinterpret_cast<unsigned*>(&b);
            plane[(size_t)(ppb + i) * 2 + (h & 1)] = v;
        }
    } else {
        int idx = (bid - SRC_PACK_BLOCKS) * 256 + threadIdx.x;  // q*(N/4)+n4
        int n4 = idx % (N / 4);
        int q = idx / (N / 4);
        int n = n4 * 4;
        const float* p = cur + (size_t)(4 * q) * N + n;
        float4 c0 = *reinterpret_cast<const float4*>(p);
        float4 c1 = *reinterpret_cast<const float4*>(p + N);
        float4 c2 = *reinterpret_cast<const float4*>(p + 2 * N);
        float4 c3 = *reinterpret_cast<const float4*>(p + 3 * N);
        const float* e0 = &c0.x; const float* e1 = &c1.x;
        const float* e2 = &c2.x; const float* e3 = &c3.x;
#pragma unroll
        for (int i = 0; i < 4; i++) {
            __half2 a = __floats2half2_rn(e0[i], e1[i]);
            __half2 b = __floats2half2_rn(e2[i], e3[i]);
            g_curh[(n + i) * 8 + 2 * q + 0] = *reinterpret_cast<unsigned*>(&a);
            g_curh[(n + i) * 8 + 2 * q + 1] = *reinterpret_cast<unsigned*>(&b);
        }
    }
}

// ---------------------------------------------------------------- fp16 dot
__device__ __forceinline__ void blend_dot_h(float& acc0, float& acc1,
                                            const uint4& t00, const uint4& t10,
                                            const uint4& t01, const uint4& t11,
                                            __half2 h00, __half2 h10,
                                            __half2 h01, __half2 h11,
                                            const uint4& curp) {
    __half2 p[4];
#pragma unroll
    for (int j = 0; j < 4; j++) {
        __half2 a = *(reinterpret_cast<const __half2*>(&t00.x) + j);
        __half2 b = *(reinterpret_cast<const __half2*>(&t10.x) + j);
        __half2 c = *(reinterpret_cast<const __half2*>(&t01.x) + j);
        __half2 e = *(reinterpret_cast<const __half2*>(&t11.x) + j);
        __half2 v = __hmul2(a, h00);
        v = __hfma2(b, h10, v);
        v = __hfma2(c, h01, v);
        v = __hfma2(e, h11, v);
        __half2 cj = *(reinterpret_cast<const __half2*>(&curp.x) + j);
        p[j] = __hmul2(v, cj);
    }
    __half2 t0 = __hadd2(p[0], p[1]);
    __half2 t1 = __hadd2(p[2], p[3]);
    __half2 u  = __hadd2(t0, t1);
    float2 f = __half22float2(u);
    acc0 += f.x;
    acc1 += f.y;
}

// Magic-number floor: floor(g) as int + frac in [0,1). |g| < 2^22 guaranteed.
__device__ __forceinline__ void fast_floor(float g, int& i, float& fr) {
    const float FM = 12582912.f;            // 1.5 * 2^23
    float t = g + FM;
    float r = t - FM;
    i = __float_as_int(t) - 0x4B400000;
    fr = g - r;
    if (fr < 0.f) { i -= 1; fr += 1.f; }
}

// Projection -> padded pixel index + packed fp16 weights. Branch-free.
__device__ __forceinline__ void proj_setup(float pu, float pv, float pz,
                                           int sbase, int& pp,
                                           __half2& h00, __half2& h10,
                                           __half2& h01, __half2& h11) {
    float iz = 1.f / (pz + 1e-8f);
    float gx = pu * iz - 0.5f;
    float gy = pv * iz - 0.5f;
    // Clamp into the apron: fully-OOB coords read zero pixels. NaN-safe.
    gx = fminf(fmaxf(gx, -1.5f), (float)W + 0.5f);
    gy = fminf(fmaxf(gy, -1.5f), (float)H + 0.5f);
    int x0, y0;
    float wx, wy;
    fast_floor(gx, x0, wx);
    fast_floor(gy, y0, wy);
    float zm  = (pz > 0.f) ? 1.f : 0.f;     // mask = z > 0
    float wy0 = zm * (1.f - wy);
    float wy1 = zm * wy;
    float wx0 = 1.f - wx;
    __half2 pk0 = __floats2half2_rn(wx0 * wy0, wx * wy0);
    __half2 pk1 = __floats2half2_rn(wx0 * wy1, wx * wy1);
    h00 = __low2half2(pk0);  h10 = __high2half2(pk0);
    h01 = __low2half2(pk1);  h11 = __high2half2(pk1);
    pp = sbase + (y0 + 2) * Wp + (x0 + 2);
}

// --------------------------------------------------------------- main kernel
// Lane tile: 8 x * 4 depth-pairs; thread owns depths (d, d+1).
// Block: 4 warps = 4 x-tiles -> 32 x * 8 d at one y. Grid (3, 64, 8) = 1536.
__global__ __launch_bounds__(128)
void cost_main(const float* __restrict__ exts, const float* __restrict__ Ks,
               const float* __restrict__ invK, const float* __restrict__ mnp,
               const float* __restrict__ mxp, float* __restrict__ out) {
    __shared__ float sP[S][12];
    int t = threadIdx.y * 32 + threadIdx.x;
    if (t < S * 12) {
        int s = t / 12, rc = t - 12 * s, r = rc >> 2, c = rc & 3;
        float accm = 0.f;
#pragma unroll
        for (int k = 0; k < 4; k++)
            accm += Ks[s * 16 + r * 4 + k] * exts[s * 16 + k * 4 + c];
        sP[s][rc] = accm;
    }
    __syncthreads();

    int lane = threadIdx.x;
    int xloc = lane & 7;            // 0..7 within-warp x
    int dloc = lane >> 3;           // 0..3 within-warp depth-pair

    int x  = blockIdx.x * 32 + threadIdx.y * 8 + xloc;
    int y  = blockIdx.y;
    int d0 = blockIdx.z * 8 + dloc * 2;      // this thread: d0, d0+1
    int n  = y * W + x;

    // Log-spaced depth bins (linspace(0,1,64) ramp = d/63)
    float mnv = mnp[0], mxv = mxp[0];
    float lstep = logf(mxv / mnv) * (1.f / 63.f);
    float lmn = logf(mnv);
    float dep0 = expf(lmn + lstep * (float)d0);
    float dep1 = expf(lmn + lstep * (float)(d0 + 1));

    // Unit-depth back-projected ray
    float pxc = (float)x + 0.5f, pyc = (float)y + 0.5f;
    float rx = invK[0] * pxc + invK[1] * pyc + invK[2];
    float ry = invK[4] * pxc + invK[5] * pyc + invK[6];
    float rz = invK[8] * pxc + invK[9] * pyc + invK[10];

    // Current-frame features as fp16 pairs (8 half2 = two uint4).
    uint4 curA = *reinterpret_cast<const uint4*>(g_curh + n * 8);
    uint4 curB = *reinterpret_cast<const uint4*>(g_curh + n * 8 + 4);

    float a0 = 0.f, a1 = 0.f;   // depth d0
    float b0 = 0.f, b1 = 0.f;   // depth d0+1

#pragma unroll
    for (int s = 0; s < S; s++) {
        const float* P = sP[s];
        float au = P[0] * rx + P[1] * ry + P[2]  * rz;
        float av = P[4] * rx + P[5] * ry + P[6]  * rz;
        float az = P[8] * rx + P[9] * ry + P[10] * rz;
        int sbase = s * NP;

        int pp0, pp1;
        __half2 u00, u10, u01, u11;   // weights depth d0
        __half2 v00, v10, v01, v11;   // weights depth d0+1
        proj_setup(dep0 * au + P[3], dep0 * av + P[7], dep0 * az + P[11],
                   sbase, pp0, u00, u10, u01, u11);
        proj_setup(dep1 * au + P[3], dep1 * av + P[7], dep1 * az + P[11],
                   sbase, pp1, v00, v10, v01, v11);

        // Taps for depth d0 (always loaded).
        const uint4* A  = g_srcA + pp0;
        const uint4* Bq = g_srcB + pp0;
        uint4 a00 = A[0],  a10 = A[1],  a01 = A[Wp],  a11 = A[Wp + 1];
        uint4 c00 = Bq[0], c10 = Bq[1], c01 = Bq[Wp], c11 = Bq[Wp + 1];

        blend_dot_h(a0, a1, a00, a10, a01, a11, u00, u10, u01, u11, curA);
        blend_dot_h(a0, a1, c00, c10, c01, c11, u00, u10, u01, u11, curB);

        // Depth d0+1: reload ONLY if its bilinear indices differ.
        // When pp1 == pp0 the tap data is identical -> results bitwise equal.
        if (pp1 != pp0) {
            const uint4* A1  = g_srcA + pp1;
            const uint4* B1 = g_srcB + pp1;
            a00 = A1[0];  a10 = A1[1];  a01 = A1[Wp];  a11 = A1[Wp + 1];
            c00 = B1[0];  c10 = B1[1];  c01 = B1[Wp];  c11 = B1[Wp + 1];
        }
        blend_dot_h(b0, b1, a00, a10, a01, a11, v00, v10, v01, v11, curA);
        blend_dot_h(b0, b1, c00, c10, c01, c11, v00, v10, v01, v11, curB);
    }

    out[d0 * N + n] = a0 + a1;                    // cost_volume [D,H,W]
    out[(d0 + 1) * N + n] = b0 + b1;
    out[D * N + d0 * N + n] = dep0;               // depth_planes [D,H,W]
    out[D * N + (d0 + 1) * N + n] = dep1;
}

}  // namespace cvk

extern "C" void kernel_launch(void* const* d_in, const int* in_sizes, int n_in,
                              void* d_out, int out_size) {
    using namespace cvk;
    const float* cur  = (const float*)d_in[0];  // [1,16,64,96]
    const float* src  = (const float*)d_in[1];  // [1,8,16,64,96]
    const float* exts = (const float*)d_in[2];  // [1,8,4,4]
    const float* Ks   = (const float*)d_in[3];  // [1,8,4,4]
    const float* invK = (const float*)d_in[4];  // [1,4,4]
    const float* mnp  = (const float*)d_in[5];  // [1,1,1,1]
    const float* mxp  = (const float*)d_in[6];  // [1,1,1,1]
    float* out = (float*)d_out;

    pack_all<<<SRC_PACK_BLOCKS + CUR_PACK_BLOCKS, 256>>>(src, cur);

    dim3 blk(32, 4);
    dim3 grd(W / 32, H, D / 8);   // 1536 blocks, depth-pair per thread
    cost_main<<<grd, blk>>>(exts, Ks, invK, mnp, mxp, out);
}